// round 1
// baseline (speedup 1.0000x reference)
#include <cuda_runtime.h>

// BlockSparse: out[m,n] = sum_k x[m,k] * W[n,k] * mask[n,k] + bias[n]
// M=8192, N=4096, K=4096. Mask is a fixed latin-square block pattern:
// block size 256, block (i,j) kept iff ((i+j) % 16) >= 8  (8 of 16 K-blocks
// per output column-block). We exploit this analytically: each 128x128
// output tile only iterates over the 8 surviving 256-wide K-blocks.

#define M_DIM 8192
#define N_DIM 4096
#define K_DIM 4096
#define NBLK  16
#define KBLOCK 256

#define BM 128
#define BN 128
#define BK 16

__global__ __launch_bounds__(256, 2)
void bs_sgemm_kernel(const float* __restrict__ x,
                     const float* __restrict__ w,
                     const float* __restrict__ bias,
                     float* __restrict__ out)
{
    __shared__ float As[BK][BM];   // x tile, transposed: As[k][m]
    __shared__ float Bs[BK][BN];   // w tile, transposed: Bs[k][n]

    const int tid   = threadIdx.x;          // 0..255
    const int mBase = blockIdx.y * BM;
    const int nBase = blockIdx.x * BN;

    // thread micro-tile mapping: 16x16 thread grid, each thread owns an
    // 8x8 accumulator split as rows {ty*4..+3, 64+ty*4..+3} and
    // cols {tx*4..+3, 64+tx*4..+3}  (contiguous float4 groups -> conflict-free LDS.128)
    const int tx = tid & 15;
    const int ty = tid >> 4;

    // tile-load mapping: 256 threads, each loads 2 float4 from x and 2 from w.
    // thread t: row = t/4 (and +64), col4 = (t%4)*4
    const int lrow = tid >> 2;          // 0..63
    const int lcol = (tid & 3) << 2;    // 0,4,8,12

    float acc[8][8];
#pragma unroll
    for (int i = 0; i < 8; i++)
#pragma unroll
        for (int j = 0; j < 8; j++) acc[i][j] = 0.0f;

    // which K-blocks survive for this output column-block
    const int nb = nBase / KBLOCK;   // output block-row index i in the mask

#pragma unroll 1
    for (int j = 0; j < NBLK; j++) {
        if (((nb + j) & (NBLK - 1)) < NBLK / 2) continue;   // mask: keep iff (i+j)%16 >= 8
        const int kb = j * KBLOCK;

#pragma unroll 1
        for (int kt = 0; kt < KBLOCK; kt += BK) {
            const int k0 = kb + kt;

            // ---- load x tile [BM x BK] and w tile [BN x BK], store transposed ----
#pragma unroll
            for (int r = 0; r < 2; r++) {
                const int row = lrow + r * 64;
                float4 v = *reinterpret_cast<const float4*>(
                    &x[(size_t)(mBase + row) * K_DIM + k0 + lcol]);
                As[lcol + 0][row] = v.x;
                As[lcol + 1][row] = v.y;
                As[lcol + 2][row] = v.z;
                As[lcol + 3][row] = v.w;

                float4 u = *reinterpret_cast<const float4*>(
                    &w[(size_t)(nBase + row) * K_DIM + k0 + lcol]);
                Bs[lcol + 0][row] = u.x;
                Bs[lcol + 1][row] = u.y;
                Bs[lcol + 2][row] = u.z;
                Bs[lcol + 3][row] = u.w;
            }
            __syncthreads();

            // ---- FFMA micro-kernel ----
#pragma unroll
            for (int kk = 0; kk < BK; kk++) {
                float a[8], b[8];
                *reinterpret_cast<float4*>(&a[0]) =
                    *reinterpret_cast<const float4*>(&As[kk][ty * 4]);
                *reinterpret_cast<float4*>(&a[4]) =
                    *reinterpret_cast<const float4*>(&As[kk][64 + ty * 4]);
                *reinterpret_cast<float4*>(&b[0]) =
                    *reinterpret_cast<const float4*>(&Bs[kk][tx * 4]);
                *reinterpret_cast<float4*>(&b[4]) =
                    *reinterpret_cast<const float4*>(&Bs[kk][64 + tx * 4]);
#pragma unroll
                for (int i = 0; i < 8; i++)
#pragma unroll
                    for (int jj = 0; jj < 8; jj++)
                        acc[i][jj] = fmaf(a[i], b[jj], acc[i][jj]);
            }
            __syncthreads();
        }
    }

    // ---- epilogue: add bias, write float4s ----
#pragma unroll
    for (int i = 0; i < 8; i++) {
        const int m = mBase + ((i < 4) ? (ty * 4 + i) : (64 + ty * 4 + (i - 4)));
#pragma unroll
        for (int half = 0; half < 2; half++) {
            const int n = nBase + ((half == 0) ? (tx * 4) : (64 + tx * 4));
            const float4 bv = *reinterpret_cast<const float4*>(&bias[n]);
            float4 o;
            o.x = acc[i][half * 4 + 0] + bv.x;
            o.y = acc[i][half * 4 + 1] + bv.y;
            o.z = acc[i][half * 4 + 2] + bv.z;
            o.w = acc[i][half * 4 + 3] + bv.w;
            *reinterpret_cast<float4*>(&out[(size_t)m * N_DIM + n]) = o;
        }
    }
}

extern "C" void kernel_launch(void* const* d_in, const int* in_sizes, int n_in,
                              void* d_out, int out_size)
{
    const float* x    = (const float*)d_in[0];   // [8192, 4096]
    const float* wgt  = (const float*)d_in[1];   // [4096, 4096]
    const float* bias = (const float*)d_in[2];   // [4096]
    // d_in[3] = mask: structure is the fixed latin square; handled analytically.
    float* out = (float*)d_out;                  // [8192, 4096]

    dim3 grid(N_DIM / BN, M_DIM / BM);           // 32 x 64
    bs_sgemm_kernel<<<grid, 256>>>(x, wgt, bias, out);
}

// round 3
// speedup vs baseline: 2.4164x; 2.4164x over previous
#include <cuda_runtime.h>
#include <cuda_bf16.h>
#include <cstdint>

// BlockSparse: out = x @ (mask*W)^T + bias.  M=8192, N=4096, K=4096 fp32.
// Mask: 256-blocks, keep (i,j) iff (i+j)%16 >= 8 -> K_eff = 2048 per column block.
//
// Toolchain constraint discovered in R2: GPU-side build targets base sm_103 PTX,
// where tcgen05.ld/st/wait/dealloc are rejected (TMEM unreadable). So we use the
// family-portable tensor-core path: mma.sync.m16n8k16 bf16 (HMMA).
//
// Precision: fp32 -> bf16 hi/lo split (prepass), 3-pass MMA:
//   x*w ~= xh*wh + xh*wl + xl*wh   (residual xl*wl ~ 2^-18 -> rel_err ~1e-5)

#define M_DIM 8192
#define N_DIM 4096
#define K_DIM 4096

#define BM 128
#define BN 128
#define BK 32
#define NCHUNKS 64                        // 8 surviving blocks * (256/32)
#define STAGES 4
#define PART_BYTES (128 * 64)             // 128 rows x 32 bf16 (64B) = 8 KB
#define STAGE_BYTES (4 * PART_BYTES)      // Ah, Al, Bh, Bl = 32 KB
#define SMEM_DYN (STAGES * STAGE_BYTES + 1024)

// device scratch for the bf16 split (allocation-free rule)
__device__ __nv_bfloat16 g_x_hi[(size_t)M_DIM * K_DIM];
__device__ __nv_bfloat16 g_x_lo[(size_t)M_DIM * K_DIM];
__device__ __nv_bfloat16 g_w_hi[(size_t)N_DIM * K_DIM];
__device__ __nv_bfloat16 g_w_lo[(size_t)N_DIM * K_DIM];

// ---------- helpers ----------
__device__ __forceinline__ uint32_t smem_u32(const void* p) {
    uint32_t a;
    asm("{ .reg .u64 t; cvta.to.shared.u64 t, %1; cvt.u32.u64 %0, t; }" : "=r"(a) : "l"(p));
    return a;
}
__device__ __forceinline__ void cp16(uint32_t dst, const void* src) {
    asm volatile("cp.async.cg.shared.global [%0], [%1], 16;" :: "r"(dst), "l"(src));
}
__device__ __forceinline__ void cp_commit() { asm volatile("cp.async.commit_group;" ::: "memory"); }
template <int N> __device__ __forceinline__ void cp_wait() {
    asm volatile("cp.async.wait_group %0;" :: "n"(N) : "memory");
}
__device__ __forceinline__ void ldsm_x4(uint32_t* r, uint32_t addr) {
    asm volatile("ldmatrix.sync.aligned.m8n8.x4.shared.b16 {%0,%1,%2,%3}, [%4];"
                 : "=r"(r[0]), "=r"(r[1]), "=r"(r[2]), "=r"(r[3]) : "r"(addr));
}
__device__ __forceinline__ void mma_bf16(float* c, const uint32_t* a, const uint32_t* b) {
    asm volatile(
        "mma.sync.aligned.m16n8k16.row.col.f32.bf16.bf16.f32 "
        "{%0,%1,%2,%3}, {%4,%5,%6,%7}, {%8,%9}, {%0,%1,%2,%3};"
        : "+f"(c[0]), "+f"(c[1]), "+f"(c[2]), "+f"(c[3])
        : "r"(a[0]), "r"(a[1]), "r"(a[2]), "r"(a[3]), "r"(b[0]), "r"(b[1]));
}
// swizzled byte offset inside an 8KB part: row r (0..127, 64B rows), 16B chunk c (0..3)
__device__ __forceinline__ uint32_t swz(int r, int c) {
    return (uint32_t)(r * 64 + ((c ^ ((r >> 1) & 3)) << 4));
}

// ---------- prepass: fp32 -> bf16 hi/lo ----------
__global__ __launch_bounds__(256) void split_kernel(const float* __restrict__ src,
                                                    long n4, int which) {
    __nv_bfloat16* hi = which ? g_w_hi : g_x_hi;
    __nv_bfloat16* lo = which ? g_w_lo : g_x_lo;
    long stride = (long)gridDim.x * blockDim.x;
    for (long j = (long)blockIdx.x * blockDim.x + threadIdx.x; j < n4; j += stride) {
        float4 v = reinterpret_cast<const float4*>(src)[j];
        float f[4] = {v.x, v.y, v.z, v.w};
        ushort hu[4], lu[4];
#pragma unroll
        for (int q = 0; q < 4; q++) {
            __nv_bfloat16 h = __float2bfloat16(f[q]);
            __nv_bfloat16 l = __float2bfloat16(f[q] - __bfloat162float(h));
            hu[q] = __bfloat16_as_ushort(h);
            lu[q] = __bfloat16_as_ushort(l);
        }
        reinterpret_cast<ushort4*>(hi)[j] = make_ushort4(hu[0], hu[1], hu[2], hu[3]);
        reinterpret_cast<ushort4*>(lo)[j] = make_ushort4(lu[0], lu[1], lu[2], lu[3]);
    }
}

// ---------- main GEMM ----------
__global__ __launch_bounds__(256, 1)
void bs_mma_kernel(const float* __restrict__ bias, float* __restrict__ out) {
    extern __shared__ char smem[];
    const uint32_t sbase = smem_u32(smem);
    float* sbias = reinterpret_cast<float*>(smem + STAGES * STAGE_BYTES);

    const int tid = threadIdx.x;
    const int wid = tid >> 5;
    const int lane = tid & 31;
    const int nBase = blockIdx.x * BN;
    const int mBase = blockIdx.y * BM;
    const int wm = wid & 3;      // 0..3 over M (32 rows each)
    const int wn = wid >> 2;     // 0..1 over N (64 cols each)

    // surviving K blocks for this column block
    int ks[8];
    {
        int n = 0;
        const int i = blockIdx.x >> 1;   // 256-block column index
#pragma unroll
        for (int j = 0; j < 16; j++)
            if (((i + j) & 15) >= 8) ks[n++] = j * 256;
    }

    if (tid < 32) {
        *reinterpret_cast<float4*>(&sbias[tid * 4]) =
            *reinterpret_cast<const float4*>(&bias[nBase + tid * 4]);
    }

    // loader: 2048 x 16B per stage, 8 per thread
    auto load_chunk = [&](int c, int s) {
        const int k0 = ks[c >> 3] + (c & 7) * BK;
        const uint32_t st = sbase + (uint32_t)s * STAGE_BYTES;
#pragma unroll
        for (int i = 0; i < 8; i++) {
            const int idx = tid + i * 256;           // 0..2047
            const int part = idx >> 9;               // 0=Ah 1=Al 2=Bh 3=Bl
            const int p = idx & 511;
            const int r = p >> 2;
            const int cc = p & 3;
            const __nv_bfloat16* src;
            if (part < 2)
                src = (part ? g_x_lo : g_x_hi) + ((size_t)(mBase + r) * K_DIM + k0 + cc * 8);
            else
                src = ((part & 1) ? g_w_lo : g_w_hi) + ((size_t)(nBase + r) * K_DIM + k0 + cc * 8);
            cp16(st + part * PART_BYTES + swz(r, cc), src);
        }
        cp_commit();
    };

    float acc[2][8][4];
#pragma unroll
    for (int a = 0; a < 2; a++)
#pragma unroll
        for (int b = 0; b < 8; b++)
#pragma unroll
            for (int q = 0; q < 4; q++) acc[a][b][q] = 0.0f;

    load_chunk(0, 0);
    load_chunk(1, 1);
    load_chunk(2, 2);

#pragma unroll 1
    for (int c = 0; c < NCHUNKS; c++) {
        if (c >= NCHUNKS - 1) cp_wait<0>(); else cp_wait<2>();
        __syncthreads();
        if (c + 3 < NCHUNKS) load_chunk(c + 3, (c + 3) & (STAGES - 1));

        const uint32_t st = sbase + (uint32_t)(c & (STAGES - 1)) * STAGE_BYTES;
#pragma unroll
        for (int kstep = 0; kstep < 2; kstep++) {
            const int c0 = kstep * 2;
            // A fragments (hi, lo): 2 m16 tiles each
            uint32_t ah[2][4], al[2][4];
#pragma unroll
            for (int mi = 0; mi < 2; mi++) {
                const int j = lane >> 3;
                const int rr = wm * 32 + mi * 16 + ((j & 1) << 3) + (lane & 7);
                const int cc = c0 + (j >> 1);
                ldsm_x4(ah[mi], st + 0 * PART_BYTES + swz(rr, cc));
                ldsm_x4(al[mi], st + 1 * PART_BYTES + swz(rr, cc));
            }
            // B fragments (hi, lo): 8 n8 tiles each (loaded as 4 x4-ldmatrix)
            uint32_t bh[8][2], bl[8][2];
#pragma unroll
            for (int nip = 0; nip < 4; nip++) {
                const int j = lane >> 3;
                const int rr = wn * 64 + nip * 16 + ((j >> 1) << 3) + (lane & 7);
                const int cc = c0 + (j & 1);
                uint32_t t[4];
                ldsm_x4(t, st + 2 * PART_BYTES + swz(rr, cc));
                bh[nip * 2][0] = t[0]; bh[nip * 2][1] = t[1];
                bh[nip * 2 + 1][0] = t[2]; bh[nip * 2 + 1][1] = t[3];
                ldsm_x4(t, st + 3 * PART_BYTES + swz(rr, cc));
                bl[nip * 2][0] = t[0]; bl[nip * 2][1] = t[1];
                bl[nip * 2 + 1][0] = t[2]; bl[nip * 2 + 1][1] = t[3];
            }
            // 3-pass MMA
#pragma unroll
            for (int mi = 0; mi < 2; mi++)
#pragma unroll
                for (int ni = 0; ni < 8; ni++) {
                    mma_bf16(acc[mi][ni], ah[mi], bh[ni]);
                    mma_bf16(acc[mi][ni], ah[mi], bl[ni]);
                    mma_bf16(acc[mi][ni], al[mi], bh[ni]);
                }
        }
        __syncthreads();
    }

    // epilogue: + bias, float2 stores
    const int qid = lane >> 2;
    const int qn = (lane & 3) * 2;
#pragma unroll
    for (int mi = 0; mi < 2; mi++) {
        const int m0 = mBase + wm * 32 + mi * 16 + qid;
#pragma unroll
        for (int ni = 0; ni < 8; ni++) {
            const int ncol = wn * 64 + ni * 8 + qn;
            const float b0 = sbias[ncol], b1 = sbias[ncol + 1];
            float2 o0 = make_float2(acc[mi][ni][0] + b0, acc[mi][ni][1] + b1);
            float2 o1 = make_float2(acc[mi][ni][2] + b0, acc[mi][ni][3] + b1);
            *reinterpret_cast<float2*>(&out[(size_t)m0 * N_DIM + nBase + ncol]) = o0;
            *reinterpret_cast<float2*>(&out[(size_t)(m0 + 8) * N_DIM + nBase + ncol]) = o1;
        }
    }
}

// ---------- launch ----------
extern "C" void kernel_launch(void* const* d_in, const int* in_sizes, int n_in,
                              void* d_out, int out_size) {
    const float* x    = (const float*)d_in[0];
    const float* w    = (const float*)d_in[1];
    const float* bias = (const float*)d_in[2];
    float* out = (float*)d_out;

    split_kernel<<<4096, 256>>>(x, (long)M_DIM * K_DIM / 4, 0);
    split_kernel<<<2048, 256>>>(w, (long)N_DIM * K_DIM / 4, 1);

    cudaFuncSetAttribute(bs_mma_kernel, cudaFuncAttributeMaxDynamicSharedMemorySize, SMEM_DYN);
    dim3 grid(N_DIM / BN, M_DIM / BM);   // 32 x 64
    bs_mma_kernel<<<grid, 256, SMEM_DYN>>>(bias, out);
}

// round 4
// speedup vs baseline: 2.8206x; 1.1673x over previous
#include <cuda_runtime.h>
#include <cuda_bf16.h>
#include <cstdint>

// BlockSparse: out = x @ (mask*W)^T + bias.  M=8192, N=4096, K=4096 fp32.
// Mask: 256-blocks, keep (i,j) iff (i+j)%16 >= 8 -> K_eff = 2048 per column block.
// Path: bf16 hi/lo split + mma.sync.m16n8k16 (family-portable; tcgen05.ld is
// rejected by the base-sm_103 PTX target this harness compiles with).
// R4: CTA 128x256, warp tile 64x64 -> 1.5x less ldmatrix traffic per MMA.

#define M_DIM 8192
#define N_DIM 4096
#define K_DIM 4096

#define BM 128
#define BN 256
#define BK 32
#define NCHUNKS 64                        // 8 surviving blocks * (256/32)
#define STAGES 4
#define A_PART (128 * 64)                 // 8 KB (128 rows x 32 bf16)
#define B_PART (256 * 64)                 // 16 KB
#define OFF_AH 0
#define OFF_AL (A_PART)
#define OFF_BH (2 * A_PART)
#define OFF_BL (2 * A_PART + B_PART)
#define STAGE_BYTES (2 * A_PART + 2 * B_PART)   // 48 KB
#define SMEM_DYN (STAGES * STAGE_BYTES + 2048)

__device__ __nv_bfloat16 g_x_hi[(size_t)M_DIM * K_DIM];
__device__ __nv_bfloat16 g_x_lo[(size_t)M_DIM * K_DIM];
__device__ __nv_bfloat16 g_w_hi[(size_t)N_DIM * K_DIM];
__device__ __nv_bfloat16 g_w_lo[(size_t)N_DIM * K_DIM];

// ---------- helpers ----------
__device__ __forceinline__ uint32_t smem_u32(const void* p) {
    uint32_t a;
    asm("{ .reg .u64 t; cvta.to.shared.u64 t, %1; cvt.u32.u64 %0, t; }" : "=r"(a) : "l"(p));
    return a;
}
__device__ __forceinline__ void cp16(uint32_t dst, const void* src) {
    asm volatile("cp.async.cg.shared.global [%0], [%1], 16;" :: "r"(dst), "l"(src));
}
__device__ __forceinline__ void cp_commit() { asm volatile("cp.async.commit_group;" ::: "memory"); }
template <int N> __device__ __forceinline__ void cp_wait() {
    asm volatile("cp.async.wait_group %0;" :: "n"(N) : "memory");
}
__device__ __forceinline__ void ldsm_x4(uint32_t* r, uint32_t addr) {
    asm volatile("ldmatrix.sync.aligned.m8n8.x4.shared.b16 {%0,%1,%2,%3}, [%4];"
                 : "=r"(r[0]), "=r"(r[1]), "=r"(r[2]), "=r"(r[3]) : "r"(addr));
}
__device__ __forceinline__ void mma_bf16(float* c, const uint32_t* a, const uint32_t* b) {
    asm volatile(
        "mma.sync.aligned.m16n8k16.row.col.f32.bf16.bf16.f32 "
        "{%0,%1,%2,%3}, {%4,%5,%6,%7}, {%8,%9}, {%0,%1,%2,%3};"
        : "+f"(c[0]), "+f"(c[1]), "+f"(c[2]), "+f"(c[3])
        : "r"(a[0]), "r"(a[1]), "r"(a[2]), "r"(a[3]), "r"(b[0]), "r"(b[1]));
}
// swizzled byte offset: 64B rows (4 x 16B chunks), XOR chunk with (row>>1)&3
__device__ __forceinline__ uint32_t swz(int r, int c) {
    return (uint32_t)(r * 64 + ((c ^ ((r >> 1) & 3)) << 4));
}

// ---------- prepass: fp32 -> bf16 hi/lo ----------
__global__ __launch_bounds__(256) void split_kernel(const float* __restrict__ src,
                                                    long n4, int which) {
    __nv_bfloat16* hi = which ? g_w_hi : g_x_hi;
    __nv_bfloat16* lo = which ? g_w_lo : g_x_lo;
    long stride = (long)gridDim.x * blockDim.x;
    for (long j = (long)blockIdx.x * blockDim.x + threadIdx.x; j < n4; j += stride) {
        float4 v = reinterpret_cast<const float4*>(src)[j];
        float f[4] = {v.x, v.y, v.z, v.w};
        ushort hu[4], lu[4];
#pragma unroll
        for (int q = 0; q < 4; q++) {
            __nv_bfloat16 h = __float2bfloat16(f[q]);
            __nv_bfloat16 l = __float2bfloat16(f[q] - __bfloat162float(h));
            hu[q] = __bfloat16_as_ushort(h);
            lu[q] = __bfloat16_as_ushort(l);
        }
        reinterpret_cast<ushort4*>(hi)[j] = make_ushort4(hu[0], hu[1], hu[2], hu[3]);
        reinterpret_cast<ushort4*>(lo)[j] = make_ushort4(lu[0], lu[1], lu[2], lu[3]);
    }
}

// ---------- main GEMM ----------
__global__ __launch_bounds__(256, 1)
void bs_mma_kernel(const float* __restrict__ bias, float* __restrict__ out) {
    extern __shared__ char smem[];
    const uint32_t sbase = smem_u32(smem);
    float* sbias = reinterpret_cast<float*>(smem + STAGES * STAGE_BYTES);

    const int tid = threadIdx.x;
    const int wid = tid >> 5;
    const int lane = tid & 31;
    const int nBase = blockIdx.x * BN;
    const int mBase = blockIdx.y * BM;
    const int wm = wid & 1;      // 0..1 over M (64 rows each)
    const int wn = wid >> 1;     // 0..3 over N (64 cols each)

    // surviving K blocks: column-block index i = blockIdx.x (BN==256)
    int ks[8];
    {
        int n = 0;
        const int i = blockIdx.x;
#pragma unroll
        for (int j = 0; j < 16; j++)
            if (((i + j) & 15) >= 8) ks[n++] = j * 256;
    }

    if (tid < 64) {
        *reinterpret_cast<float4*>(&sbias[tid * 4]) =
            *reinterpret_cast<const float4*>(&bias[nBase + tid * 4]);
    }

    // loader: 3072 x 16B per stage, 12 per thread
    auto load_chunk = [&](int c, int s) {
        const int k0 = ks[c >> 3] + (c & 7) * BK;
        const uint32_t st = sbase + (uint32_t)s * STAGE_BYTES;
#pragma unroll
        for (int i = 0; i < 12; i++) {
            const int idx = tid + i * 256;             // 0..3071
            uint32_t dst;
            const __nv_bfloat16* src;
            if (idx < 1024) {                          // A: hi then lo (512 each)
                const int half = idx >> 9;
                const int p = idx & 511;
                const int r = p >> 2, cc = p & 3;
                src = (half ? g_x_lo : g_x_hi) + ((size_t)(mBase + r) * K_DIM + k0 + cc * 8);
                dst = st + (half ? OFF_AL : OFF_AH) + swz(r, cc);
            } else {                                   // B: hi then lo (1024 each)
                const int t = idx - 1024;
                const int half = t >> 10;
                const int p = t & 1023;
                const int r = p >> 2, cc = p & 3;
                src = (half ? g_w_lo : g_w_hi) + ((size_t)(nBase + r) * K_DIM + k0 + cc * 8);
                dst = st + (half ? OFF_BL : OFF_BH) + swz(r, cc);
            }
            cp16(dst, src);
        }
        cp_commit();
    };

    float acc[4][8][4];
#pragma unroll
    for (int a = 0; a < 4; a++)
#pragma unroll
        for (int b = 0; b < 8; b++)
#pragma unroll
            for (int q = 0; q < 4; q++) acc[a][b][q] = 0.0f;

    load_chunk(0, 0);
    load_chunk(1, 1);
    load_chunk(2, 2);

    const int j = lane >> 3;          // ldmatrix quadrant 0..3
    const int l7 = lane & 7;

#pragma unroll 1
    for (int c = 0; c < NCHUNKS; c++) {
        if (c >= NCHUNKS - 1) cp_wait<0>(); else cp_wait<2>();
        __syncthreads();
        if (c + 3 < NCHUNKS) load_chunk(c + 3, (c + 3) & (STAGES - 1));

        const uint32_t st = sbase + (uint32_t)(c & (STAGES - 1)) * STAGE_BYTES;
#pragma unroll
        for (int kstep = 0; kstep < 2; kstep++) {
            const int c0 = kstep * 2;
            // A fragments: 4 m16 tiles, hi and lo
            uint32_t ah[4][4], al[4][4];
#pragma unroll
            for (int mi = 0; mi < 4; mi++) {
                const int rr = wm * 64 + mi * 16 + ((j & 1) << 3) + l7;
                const int cc = c0 + (j >> 1);
                ldsm_x4(ah[mi], st + OFF_AH + swz(rr, cc));
                ldsm_x4(al[mi], st + OFF_AL + swz(rr, cc));
            }
            // B: per 16-col group, load hi+lo then consume immediately
#pragma unroll
            for (int nip = 0; nip < 4; nip++) {
                const int rr = wn * 64 + nip * 16 + ((j >> 1) << 3) + l7;
                const int cc = c0 + (j & 1);
                uint32_t bh[4], bl[4];
                ldsm_x4(bh, st + OFF_BH + swz(rr, cc));
                ldsm_x4(bl, st + OFF_BL + swz(rr, cc));
#pragma unroll
                for (int half = 0; half < 2; half++) {
                    const int ni = nip * 2 + half;
#pragma unroll
                    for (int mi = 0; mi < 4; mi++) {
                        mma_bf16(acc[mi][ni], ah[mi], &bh[half * 2]);
                        mma_bf16(acc[mi][ni], ah[mi], &bl[half * 2]);
                        mma_bf16(acc[mi][ni], al[mi], &bh[half * 2]);
                    }
                }
            }
        }
    }

    // epilogue
    const int qid = lane >> 2;
    const int qn = (lane & 3) * 2;
#pragma unroll
    for (int mi = 0; mi < 4; mi++) {
        const int m0 = mBase + wm * 64 + mi * 16 + qid;
#pragma unroll
        for (int ni = 0; ni < 8; ni++) {
            const int ncol = wn * 64 + ni * 8 + qn;
            const float b0 = sbias[ncol], b1 = sbias[ncol + 1];
            float2 o0 = make_float2(acc[mi][ni][0] + b0, acc[mi][ni][1] + b1);
            float2 o1 = make_float2(acc[mi][ni][2] + b0, acc[mi][ni][3] + b1);
            *reinterpret_cast<float2*>(&out[(size_t)m0 * N_DIM + nBase + ncol]) = o0;
            *reinterpret_cast<float2*>(&out[(size_t)(m0 + 8) * N_DIM + nBase + ncol]) = o1;
        }
    }
}

// ---------- launch ----------
extern "C" void kernel_launch(void* const* d_in, const int* in_sizes, int n_in,
                              void* d_out, int out_size) {
    const float* x    = (const float*)d_in[0];
    const float* w    = (const float*)d_in[1];
    const float* bias = (const float*)d_in[2];
    float* out = (float*)d_out;

    split_kernel<<<4096, 256>>>(x, (long)M_DIM * K_DIM / 4, 0);
    split_kernel<<<2048, 256>>>(w, (long)N_DIM * K_DIM / 4, 1);

    cudaFuncSetAttribute(bs_mma_kernel, cudaFuncAttributeMaxDynamicSharedMemorySize, SMEM_DYN);
    dim3 grid(N_DIM / BN, M_DIM / BM);   // 16 x 64
    bs_mma_kernel<<<grid, 256, SMEM_DYN>>>(bias, out);
}

// round 5
// speedup vs baseline: 3.9290x; 1.3929x over previous
#include <cuda_runtime.h>
#include <cuda_bf16.h>
#include <cstdint>

// BlockSparse: out = x @ (mask*W)^T + bias.  M=8192, N=4096, K=4096 fp32.
// Mask: 256-blocks, keep (i,j) iff (i+j)%16 >= 8 -> K_eff = 2048 per column block.
//
// R5: single-pass TF32 mma.sync.m16n8k8 (inputs pre-rounded with cvt.rna in a
// prepass). 3x fewer MMA FLOP-passes than the bf16 hi/lo approach; rel_err ~1e-4.
// ldmatrix trick: m8n8.b16 over an 8x4 fp32 quadrant delivers one full fp32
// element per lane at (t/4, t%4) == the tf32 fragment layout.

#define M_DIM 8192
#define N_DIM 4096
#define K_DIM 4096

#define BM 128
#define BN 256
#define BK 32
#define NCHUNKS 64                        // 8 surviving 256-blocks * (256/32)
#define STAGES 4
#define A_PART (128 * 128)                // 128 rows x 32 fp32 (128B) = 16 KB
#define B_PART (256 * 128)                // 32 KB
#define OFF_A 0
#define OFF_B (A_PART)
#define STAGE_BYTES (A_PART + B_PART)     // 48 KB
#define SMEM_DYN (STAGES * STAGE_BYTES + 2048)

// tf32-rounded copies (scratch; allocation-free rule -> __device__ globals)
__device__ float g_x[(size_t)M_DIM * K_DIM];
__device__ float g_w[(size_t)N_DIM * K_DIM];

// ---------- helpers ----------
__device__ __forceinline__ uint32_t smem_u32(const void* p) {
    uint32_t a;
    asm("{ .reg .u64 t; cvta.to.shared.u64 t, %1; cvt.u32.u64 %0, t; }" : "=r"(a) : "l"(p));
    return a;
}
__device__ __forceinline__ void cp16(uint32_t dst, const void* src) {
    asm volatile("cp.async.cg.shared.global [%0], [%1], 16;" :: "r"(dst), "l"(src));
}
__device__ __forceinline__ void cp_commit() { asm volatile("cp.async.commit_group;" ::: "memory"); }
template <int N> __device__ __forceinline__ void cp_wait() {
    asm volatile("cp.async.wait_group %0;" :: "n"(N) : "memory");
}
__device__ __forceinline__ void ldsm_x4(uint32_t* r, uint32_t addr) {
    asm volatile("ldmatrix.sync.aligned.m8n8.x4.shared.b16 {%0,%1,%2,%3}, [%4];"
                 : "=r"(r[0]), "=r"(r[1]), "=r"(r[2]), "=r"(r[3]) : "r"(addr));
}
__device__ __forceinline__ void mma_tf32(float* c, const uint32_t* a, const uint32_t* b) {
    asm volatile(
        "mma.sync.aligned.m16n8k8.row.col.f32.tf32.tf32.f32 "
        "{%0,%1,%2,%3}, {%4,%5,%6,%7}, {%8,%9}, {%0,%1,%2,%3};"
        : "+f"(c[0]), "+f"(c[1]), "+f"(c[2]), "+f"(c[3])
        : "r"(a[0]), "r"(a[1]), "r"(a[2]), "r"(a[3]), "r"(b[0]), "r"(b[1]));
}
__device__ __forceinline__ float tf32_rna(float f) {
    uint32_t o;
    asm("cvt.rna.tf32.f32 %0, %1;" : "=r"(o) : "f"(f));
    return __uint_as_float(o);
}
// 128B rows = 8 x 16B chunks; physical chunk = c ^ (r & 7) -> ldmatrix conflict-free
__device__ __forceinline__ uint32_t swz(int r, int c) {
    return (uint32_t)(r * 128 + ((c ^ (r & 7)) << 4));
}

// ---------- prepass: fp32 -> tf32(rna)-rounded fp32 ----------
__global__ __launch_bounds__(256) void cvt_kernel(const float* __restrict__ src,
                                                  long n4, int which) {
    float* dst = which ? g_w : g_x;
    long stride = (long)gridDim.x * blockDim.x;
    for (long j = (long)blockIdx.x * blockDim.x + threadIdx.x; j < n4; j += stride) {
        float4 v = reinterpret_cast<const float4*>(src)[j];
        v.x = tf32_rna(v.x); v.y = tf32_rna(v.y);
        v.z = tf32_rna(v.z); v.w = tf32_rna(v.w);
        reinterpret_cast<float4*>(dst)[j] = v;
    }
}

// ---------- main GEMM ----------
__global__ __launch_bounds__(256, 1)
void bs_tf32_kernel(const float* __restrict__ bias, float* __restrict__ out) {
    extern __shared__ char smem[];
    const uint32_t sbase = smem_u32(smem);
    float* sbias = reinterpret_cast<float*>(smem + STAGES * STAGE_BYTES);

    const int tid = threadIdx.x;
    const int wid = tid >> 5;
    const int lane = tid & 31;
    const int nBase = blockIdx.x * BN;
    const int mBase = blockIdx.y * BM;
    const int wm = wid & 1;      // 0..1 over M (64 rows)
    const int wn = wid >> 1;     // 0..3 over N (64 cols)

    int ks[8];
    {
        int n = 0;
        const int i = blockIdx.x;     // 256-block column index (BN==256)
#pragma unroll
        for (int j = 0; j < 16; j++)
            if (((i + j) & 15) >= 8) ks[n++] = j * 256;
    }

    if (tid < 64) {
        *reinterpret_cast<float4*>(&sbias[tid * 4]) =
            *reinterpret_cast<const float4*>(&bias[nBase + tid * 4]);
    }

    // loader: 3072 x 16B per stage (A:1024, B:2048), 12 per thread
    auto load_chunk = [&](int c, int s) {
        const int k0 = ks[c >> 3] + (c & 7) * BK;
        const uint32_t st = sbase + (uint32_t)s * STAGE_BYTES;
#pragma unroll
        for (int i = 0; i < 12; i++) {
            const int idx = tid + i * 256;             // 0..3071
            uint32_t dst;
            const float* src;
            if (idx < 1024) {                          // A: 128 rows x 8 chunks
                const int r = idx >> 3, cc = idx & 7;
                src = g_x + ((size_t)(mBase + r) * K_DIM + k0 + cc * 4);
                dst = st + OFF_A + swz(r, cc);
            } else {                                   // B: 256 rows x 8 chunks
                const int t = idx - 1024;
                const int r = t >> 3, cc = t & 7;
                src = g_w + ((size_t)(nBase + r) * K_DIM + k0 + cc * 4);
                dst = st + OFF_B + swz(r, cc);
            }
            cp16(dst, src);
        }
        cp_commit();
    };

    float acc[4][8][4];
#pragma unroll
    for (int a = 0; a < 4; a++)
#pragma unroll
        for (int b = 0; b < 8; b++)
#pragma unroll
            for (int q = 0; q < 4; q++) acc[a][b][q] = 0.0f;

    load_chunk(0, 0);
    load_chunk(1, 1);
    load_chunk(2, 2);

    const int q = lane >> 3;     // ldmatrix quadrant 0..3
    const int l7 = lane & 7;

#pragma unroll 1
    for (int c = 0; c < NCHUNKS; c++) {
        if (c >= NCHUNKS - 1) cp_wait<0>(); else cp_wait<2>();
        __syncthreads();
        if (c + 3 < NCHUNKS) load_chunk(c + 3, (c + 3) & (STAGES - 1));

        const uint32_t st = sbase + (uint32_t)(c & (STAGES - 1)) * STAGE_BYTES;
#pragma unroll
        for (int kstep = 0; kstep < 4; kstep++) {       // 4 x k8
            const int c0 = kstep * 2;                   // 16B-chunk pair {c0, c0+1}
            // A fragments: 4 m16 tiles; x4 quadrants: (q&1)->row half, (q>>1)->k half
            uint32_t af[4][4];
#pragma unroll
            for (int mi = 0; mi < 4; mi++) {
                const int rr = wm * 64 + mi * 16 + ((q & 1) << 3) + l7;
                ldsm_x4(af[mi], st + OFF_A + swz(rr, c0 + (q >> 1)));
            }
            // B: x4 covers two n8 tiles: lanes 0-15 tile0 (k-lo,k-hi), 16-31 tile1
#pragma unroll
            for (int nip = 0; nip < 4; nip++) {
                const int rr = wn * 64 + nip * 16 + ((q >> 1) << 3) + l7;
                uint32_t bf[4];
                ldsm_x4(bf, st + OFF_B + swz(rr, c0 + (q & 1)));
#pragma unroll
                for (int half = 0; half < 2; half++) {
                    const int ni = nip * 2 + half;
#pragma unroll
                    for (int mi = 0; mi < 4; mi++)
                        mma_tf32(acc[mi][ni], af[mi], &bf[half * 2]);
                }
            }
        }
    }

    // epilogue: + bias
    const int qid = lane >> 2;
    const int qn = (lane & 3) * 2;
#pragma unroll
    for (int mi = 0; mi < 4; mi++) {
        const int m0 = mBase + wm * 64 + mi * 16 + qid;
#pragma unroll
        for (int ni = 0; ni < 8; ni++) {
            const int ncol = wn * 64 + ni * 8 + qn;
            const float b0 = sbias[ncol], b1 = sbias[ncol + 1];
            float2 o0 = make_float2(acc[mi][ni][0] + b0, acc[mi][ni][1] + b1);
            float2 o1 = make_float2(acc[mi][ni][2] + b0, acc[mi][ni][3] + b1);
            *reinterpret_cast<float2*>(&out[(size_t)m0 * N_DIM + nBase + ncol]) = o0;
            *reinterpret_cast<float2*>(&out[(size_t)(m0 + 8) * N_DIM + nBase + ncol]) = o1;
        }
    }
}

// ---------- launch ----------
extern "C" void kernel_launch(void* const* d_in, const int* in_sizes, int n_in,
                              void* d_out, int out_size) {
    const float* x    = (const float*)d_in[0];
    const float* w    = (const float*)d_in[1];
    const float* bias = (const float*)d_in[2];
    float* out = (float*)d_out;

    cvt_kernel<<<4096, 256>>>(x, (long)M_DIM * K_DIM / 4, 0);
    cvt_kernel<<<2048, 256>>>(w, (long)N_DIM * K_DIM / 4, 1);

    cudaFuncSetAttribute(bs_tf32_kernel, cudaFuncAttributeMaxDynamicSharedMemorySize, SMEM_DYN);
    dim3 grid(N_DIM / BN, M_DIM / BM);   // 16 x 64
    bs_tf32_kernel<<<grid, 256, SMEM_DYN>>>(bias, out);
}

// round 6
// speedup vs baseline: 4.1765x; 1.0630x over previous
#include <cuda_runtime.h>
#include <cuda_bf16.h>
#include <cstdint>

// BlockSparse: out = x @ (mask*W)^T + bias.  M=8192, N=4096, K=4096 fp32.
// Mask: 256-blocks, keep (i,j) iff (i+j)%16 >= 8 -> K_eff = 2048 per column block.
//
// R6: single-pass TF32 m16n8k8, 512 threads (4 warps/SMSP) to saturate the
// legacy-HMMA issue pipe. Warp tile 64x32. cvt.rna prepass for accuracy.

#define M_DIM 8192
#define N_DIM 4096
#define K_DIM 4096

#define BM 128
#define BN 256
#define BK 32
#define NCHUNKS 64
#define STAGES 4
#define A_PART (128 * 128)                // 16 KB
#define B_PART (256 * 128)                // 32 KB
#define OFF_A 0
#define OFF_B (A_PART)
#define STAGE_BYTES (A_PART + B_PART)     // 48 KB
#define SMEM_DYN (STAGES * STAGE_BYTES + 2048)

__device__ float g_x[(size_t)M_DIM * K_DIM];
__device__ float g_w[(size_t)N_DIM * K_DIM];

// ---------- helpers ----------
__device__ __forceinline__ uint32_t smem_u32(const void* p) {
    uint32_t a;
    asm("{ .reg .u64 t; cvta.to.shared.u64 t, %1; cvt.u32.u64 %0, t; }" : "=r"(a) : "l"(p));
    return a;
}
__device__ __forceinline__ void cp16(uint32_t dst, const void* src) {
    asm volatile("cp.async.cg.shared.global [%0], [%1], 16;" :: "r"(dst), "l"(src));
}
__device__ __forceinline__ void cp_commit() { asm volatile("cp.async.commit_group;" ::: "memory"); }
template <int N> __device__ __forceinline__ void cp_wait() {
    asm volatile("cp.async.wait_group %0;" :: "n"(N) : "memory");
}
__device__ __forceinline__ void ldsm_x4(uint32_t* r, uint32_t addr) {
    asm volatile("ldmatrix.sync.aligned.m8n8.x4.shared.b16 {%0,%1,%2,%3}, [%4];"
                 : "=r"(r[0]), "=r"(r[1]), "=r"(r[2]), "=r"(r[3]) : "r"(addr));
}
__device__ __forceinline__ void mma_tf32(float* c, const uint32_t* a, const uint32_t* b) {
    asm volatile(
        "mma.sync.aligned.m16n8k8.row.col.f32.tf32.tf32.f32 "
        "{%0,%1,%2,%3}, {%4,%5,%6,%7}, {%8,%9}, {%0,%1,%2,%3};"
        : "+f"(c[0]), "+f"(c[1]), "+f"(c[2]), "+f"(c[3])
        : "r"(a[0]), "r"(a[1]), "r"(a[2]), "r"(a[3]), "r"(b[0]), "r"(b[1]));
}
__device__ __forceinline__ float tf32_rna(float f) {
    uint32_t o;
    asm("cvt.rna.tf32.f32 %0, %1;" : "=r"(o) : "f"(f));
    return __uint_as_float(o);
}
__device__ __forceinline__ uint32_t swz(int r, int c) {
    return (uint32_t)(r * 128 + ((c ^ (r & 7)) << 4));
}

// ---------- prepass ----------
__global__ __launch_bounds__(256) void cvt_kernel(const float* __restrict__ src,
                                                  long n4, int which) {
    float* dst = which ? g_w : g_x;
    long stride = (long)gridDim.x * blockDim.x;
    for (long j = (long)blockIdx.x * blockDim.x + threadIdx.x; j < n4; j += stride) {
        float4 v = reinterpret_cast<const float4*>(src)[j];
        v.x = tf32_rna(v.x); v.y = tf32_rna(v.y);
        v.z = tf32_rna(v.z); v.w = tf32_rna(v.w);
        reinterpret_cast<float4*>(dst)[j] = v;
    }
}

// ---------- main GEMM ----------
__global__ __launch_bounds__(512, 1)
void bs_tf32_kernel(const float* __restrict__ bias, float* __restrict__ out) {
    extern __shared__ char smem[];
    const uint32_t sbase = smem_u32(smem);
    float* sbias = reinterpret_cast<float*>(smem + STAGES * STAGE_BYTES);

    const int tid = threadIdx.x;
    const int wid = tid >> 5;
    const int lane = tid & 31;
    const int nBase = blockIdx.x * BN;
    const int mBase = blockIdx.y * BM;
    const int wm = wid & 1;      // 0..1 over M (64 rows)
    const int wn = wid >> 1;     // 0..7 over N (32 cols)

    int ks[8];
    {
        int n = 0;
        const int i = blockIdx.x;
#pragma unroll
        for (int j = 0; j < 16; j++)
            if (((i + j) & 15) >= 8) ks[n++] = j * 256;
    }

    if (tid < 64) {
        *reinterpret_cast<float4*>(&sbias[tid * 4]) =
            *reinterpret_cast<const float4*>(&bias[nBase + tid * 4]);
    }

    // loader: 3072 x 16B per stage, 6 per thread (512 threads)
    auto load_chunk = [&](int c, int s) {
        const int k0 = ks[c >> 3] + (c & 7) * BK;
        const uint32_t st = sbase + (uint32_t)s * STAGE_BYTES;
#pragma unroll
        for (int i = 0; i < 6; i++) {
            const int idx = tid + i * 512;             // 0..3071
            uint32_t dst;
            const float* src;
            if (idx < 1024) {                          // A
                const int r = idx >> 3, cc = idx & 7;
                src = g_x + ((size_t)(mBase + r) * K_DIM + k0 + cc * 4);
                dst = st + OFF_A + swz(r, cc);
            } else {                                   // B
                const int t = idx - 1024;
                const int r = t >> 3, cc = t & 7;
                src = g_w + ((size_t)(nBase + r) * K_DIM + k0 + cc * 4);
                dst = st + OFF_B + swz(r, cc);
            }
            cp16(dst, src);
        }
        cp_commit();
    };

    float acc[4][4][4];
#pragma unroll
    for (int a = 0; a < 4; a++)
#pragma unroll
        for (int b = 0; b < 4; b++)
#pragma unroll
            for (int p = 0; p < 4; p++) acc[a][b][p] = 0.0f;

    load_chunk(0, 0);
    load_chunk(1, 1);
    load_chunk(2, 2);

    const int q = lane >> 3;     // ldmatrix quadrant 0..3
    const int l7 = lane & 7;

#pragma unroll 1
    for (int c = 0; c < NCHUNKS; c++) {
        if (c >= NCHUNKS - 1) cp_wait<0>(); else cp_wait<2>();
        __syncthreads();
        if (c + 3 < NCHUNKS) load_chunk(c + 3, (c + 3) & (STAGES - 1));

        const uint32_t st = sbase + (uint32_t)(c & (STAGES - 1)) * STAGE_BYTES;
#pragma unroll
        for (int kstep = 0; kstep < 4; kstep++) {       // 4 x k8
            const int c0 = kstep * 2;
            // A: 4 m16 tiles (64 rows); quadrants: (q&1)->row half, (q>>1)->k half
            uint32_t af[4][4];
#pragma unroll
            for (int mi = 0; mi < 4; mi++) {
                const int rr = wm * 64 + mi * 16 + ((q & 1) << 3) + l7;
                ldsm_x4(af[mi], st + OFF_A + swz(rr, c0 + (q >> 1)));
            }
            // B: 2 x ldsm.x4, each covers two n8 tiles (16 cols)
#pragma unroll
            for (int nip = 0; nip < 2; nip++) {
                const int rr = wn * 32 + nip * 16 + ((q >> 1) << 3) + l7;
                uint32_t bf[4];
                ldsm_x4(bf, st + OFF_B + swz(rr, c0 + (q & 1)));
#pragma unroll
                for (int half = 0; half < 2; half++) {
                    const int ni = nip * 2 + half;
#pragma unroll
                    for (int mi = 0; mi < 4; mi++)
                        mma_tf32(acc[mi][ni], af[mi], &bf[half * 2]);
                }
            }
        }
    }

    // epilogue: + bias
    const int qid = lane >> 2;
    const int qn = (lane & 3) * 2;
#pragma unroll
    for (int mi = 0; mi < 4; mi++) {
        const int m0 = mBase + wm * 64 + mi * 16 + qid;
#pragma unroll
        for (int ni = 0; ni < 4; ni++) {
            const int ncol = wn * 32 + ni * 8 + qn;
            const float b0 = sbias[ncol], b1 = sbias[ncol + 1];
            float2 o0 = make_float2(acc[mi][ni][0] + b0, acc[mi][ni][1] + b1);
            float2 o1 = make_float2(acc[mi][ni][2] + b0, acc[mi][ni][3] + b1);
            *reinterpret_cast<float2*>(&out[(size_t)m0 * N_DIM + nBase + ncol]) = o0;
            *reinterpret_cast<float2*>(&out[(size_t)(m0 + 8) * N_DIM + nBase + ncol]) = o1;
        }
    }
}

// ---------- launch ----------
extern "C" void kernel_launch(void* const* d_in, const int* in_sizes, int n_in,
                              void* d_out, int out_size) {
    const float* x    = (const float*)d_in[0];
    const float* w    = (const float*)d_in[1];
    const float* bias = (const float*)d_in[2];
    float* out = (float*)d_out;

    cvt_kernel<<<4096, 256>>>(x, (long)M_DIM * K_DIM / 4, 0);
    cvt_kernel<<<2048, 256>>>(w, (long)N_DIM * K_DIM / 4, 1);

    cudaFuncSetAttribute(bs_tf32_kernel, cudaFuncAttributeMaxDynamicSharedMemorySize, SMEM_DYN);
    dim3 grid(N_DIM / BN, M_DIM / BM);   // 16 x 64
    bs_tf32_kernel<<<grid, 512, SMEM_DYN>>>(bias, out);
}

// round 7
// speedup vs baseline: 7.4969x; 1.7950x over previous
#include <cuda_runtime.h>
#include <cuda_fp16.h>
#include <cstdint>

// BlockSparse: out = x @ (mask*W)^T + bias.  M=8192, N=4096, K=4096 fp32.
// Mask: 256-blocks, keep (i,j) iff (i+j)%16 >= 8 -> K_eff = 2048 per column block.
//
// R7: single-pass FP16 m16n8k16 (f32 accumulate). fp16 has the same 10-bit
// mantissa as tf32 -> same rel_err (~3e-4), but k16 shape = half the MMA
// instructions, and the legacy mma.sync pipe charges per instruction (~10cyc
// flat, measured R4-R6). BK=64, 512 threads, warp tile 64x32, 4-stage cp.async.

#define M_DIM 8192
#define N_DIM 4096
#define K_DIM 4096

#define BM 128
#define BN 256
#define BK 64
#define NCHUNKS 32                        // 8 surviving 256-blocks * (256/64)
#define STAGES 4
#define A_PART (128 * 128)                // 128 rows x 64 fp16 (128B) = 16 KB
#define B_PART (256 * 128)                // 32 KB
#define OFF_A 0
#define OFF_B (A_PART)
#define STAGE_BYTES (A_PART + B_PART)     // 48 KB
#define SMEM_DYN (STAGES * STAGE_BYTES + 2048)

// fp16 copies (scratch; allocation-free rule -> __device__ globals)
__device__ __half g_x[(size_t)M_DIM * K_DIM];
__device__ __half g_w[(size_t)N_DIM * K_DIM];

// ---------- helpers ----------
__device__ __forceinline__ uint32_t smem_u32(const void* p) {
    uint32_t a;
    asm("{ .reg .u64 t; cvta.to.shared.u64 t, %1; cvt.u32.u64 %0, t; }" : "=r"(a) : "l"(p));
    return a;
}
__device__ __forceinline__ void cp16(uint32_t dst, const void* src) {
    asm volatile("cp.async.cg.shared.global [%0], [%1], 16;" :: "r"(dst), "l"(src));
}
__device__ __forceinline__ void cp_commit() { asm volatile("cp.async.commit_group;" ::: "memory"); }
template <int N> __device__ __forceinline__ void cp_wait() {
    asm volatile("cp.async.wait_group %0;" :: "n"(N) : "memory");
}
__device__ __forceinline__ void ldsm_x4(uint32_t* r, uint32_t addr) {
    asm volatile("ldmatrix.sync.aligned.m8n8.x4.shared.b16 {%0,%1,%2,%3}, [%4];"
                 : "=r"(r[0]), "=r"(r[1]), "=r"(r[2]), "=r"(r[3]) : "r"(addr));
}
__device__ __forceinline__ void mma_f16(float* c, const uint32_t* a, const uint32_t* b) {
    asm volatile(
        "mma.sync.aligned.m16n8k16.row.col.f32.f16.f16.f32 "
        "{%0,%1,%2,%3}, {%4,%5,%6,%7}, {%8,%9}, {%0,%1,%2,%3};"
        : "+f"(c[0]), "+f"(c[1]), "+f"(c[2]), "+f"(c[3])
        : "r"(a[0]), "r"(a[1]), "r"(a[2]), "r"(a[3]), "r"(b[0]), "r"(b[1]));
}
// 128B rows = 8 x 16B chunks; physical chunk = c ^ (r & 7) -> ldmatrix conflict-free
__device__ __forceinline__ uint32_t swz(int r, int c) {
    return (uint32_t)(r * 128 + ((c ^ (r & 7)) << 4));
}

// ---------- prepass: fp32 -> fp16 (round-to-nearest) ----------
__global__ __launch_bounds__(256) void cvt_kernel(const float* __restrict__ src,
                                                  long n4, int which) {
    __half* dst = which ? g_w : g_x;
    long stride = (long)gridDim.x * blockDim.x;
    for (long j = (long)blockIdx.x * blockDim.x + threadIdx.x; j < n4; j += stride) {
        float4 v = reinterpret_cast<const float4*>(src)[j];
        __half2 h0 = __floats2half2_rn(v.x, v.y);
        __half2 h1 = __floats2half2_rn(v.z, v.w);
        reinterpret_cast<uint2*>(dst)[j] =
            make_uint2(*reinterpret_cast<uint32_t*>(&h0), *reinterpret_cast<uint32_t*>(&h1));
    }
}

// ---------- main GEMM ----------
__global__ __launch_bounds__(512, 1)
void bs_f16_kernel(const float* __restrict__ bias, float* __restrict__ out) {
    extern __shared__ char smem[];
    const uint32_t sbase = smem_u32(smem);
    float* sbias = reinterpret_cast<float*>(smem + STAGES * STAGE_BYTES);

    const int tid = threadIdx.x;
    const int wid = tid >> 5;
    const int lane = tid & 31;
    const int nBase = blockIdx.x * BN;
    const int mBase = blockIdx.y * BM;
    const int wm = wid & 1;      // 0..1 over M (64 rows)
    const int wn = wid >> 1;     // 0..7 over N (32 cols)

    int ks[8];
    {
        int n = 0;
        const int i = blockIdx.x;     // 256-block column index (BN==256)
#pragma unroll
        for (int j = 0; j < 16; j++)
            if (((i + j) & 15) >= 8) ks[n++] = j * 256;
    }

    if (tid < 64) {
        *reinterpret_cast<float4*>(&sbias[tid * 4]) =
            *reinterpret_cast<const float4*>(&bias[nBase + tid * 4]);
    }

    // loader: 3072 x 16B per stage (A:1024, B:2048), 6 per thread (512 thr)
    auto load_chunk = [&](int c, int s) {
        const int k0 = ks[c >> 2] + (c & 3) * BK;
        const uint32_t st = sbase + (uint32_t)s * STAGE_BYTES;
#pragma unroll
        for (int i = 0; i < 6; i++) {
            const int idx = tid + i * 512;             // 0..3071
            uint32_t dst;
            const __half* src;
            if (idx < 1024) {                          // A: 128 rows x 8 chunks
                const int r = idx >> 3, cc = idx & 7;
                src = g_x + ((size_t)(mBase + r) * K_DIM + k0 + cc * 8);
                dst = st + OFF_A + swz(r, cc);
            } else {                                   // B: 256 rows x 8 chunks
                const int t = idx - 1024;
                const int r = t >> 3, cc = t & 7;
                src = g_w + ((size_t)(nBase + r) * K_DIM + k0 + cc * 8);
                dst = st + OFF_B + swz(r, cc);
            }
            cp16(dst, src);
        }
        cp_commit();
    };

    float acc[4][4][4];
#pragma unroll
    for (int a = 0; a < 4; a++)
#pragma unroll
        for (int b = 0; b < 4; b++)
#pragma unroll
            for (int p = 0; p < 4; p++) acc[a][b][p] = 0.0f;

    load_chunk(0, 0);
    load_chunk(1, 1);
    load_chunk(2, 2);

    const int q = lane >> 3;     // ldmatrix quadrant 0..3
    const int l7 = lane & 7;

#pragma unroll 1
    for (int c = 0; c < NCHUNKS; c++) {
        if (c >= NCHUNKS - 1) cp_wait<0>(); else cp_wait<2>();
        __syncthreads();
        if (c + 3 < NCHUNKS) load_chunk(c + 3, (c + 3) & (STAGES - 1));

        const uint32_t st = sbase + (uint32_t)(c & (STAGES - 1)) * STAGE_BYTES;
#pragma unroll
        for (int kstep = 0; kstep < 4; kstep++) {       // 4 x k16
            const int c0 = kstep * 2;                   // 16B-chunk pair {c0, c0+1}
            // A: 4 m16k16 tiles; quadrants: (q&1)->row half, (q>>1)->k half
            uint32_t af[4][4];
#pragma unroll
            for (int mi = 0; mi < 4; mi++) {
                const int rr = wm * 64 + mi * 16 + ((q & 1) << 3) + l7;
                ldsm_x4(af[mi], st + OFF_A + swz(rr, c0 + (q >> 1)));
            }
            // B: 2 x ldsm.x4; each covers two n8k16 tiles (16 cols)
#pragma unroll
            for (int nip = 0; nip < 2; nip++) {
                const int rr = wn * 32 + nip * 16 + ((q >> 1) << 3) + l7;
                uint32_t bf[4];
                ldsm_x4(bf, st + OFF_B + swz(rr, c0 + (q & 1)));
#pragma unroll
                for (int half = 0; half < 2; half++) {
                    const int ni = nip * 2 + half;
#pragma unroll
                    for (int mi = 0; mi < 4; mi++)
                        mma_f16(acc[mi][ni], af[mi], &bf[half * 2]);
                }
            }
        }
    }

    // epilogue: + bias
    const int qid = lane >> 2;
    const int qn = (lane & 3) * 2;
#pragma unroll
    for (int mi = 0; mi < 4; mi++) {
        const int m0 = mBase + wm * 64 + mi * 16 + qid;
#pragma unroll
        for (int ni = 0; ni < 4; ni++) {
            const int ncol = wn * 32 + ni * 8 + qn;
            const float b0 = sbias[ncol], b1 = sbias[ncol + 1];
            float2 o0 = make_float2(acc[mi][ni][0] + b0, acc[mi][ni][1] + b1);
            float2 o1 = make_float2(acc[mi][ni][2] + b0, acc[mi][ni][3] + b1);
            *reinterpret_cast<float2*>(&out[(size_t)m0 * N_DIM + nBase + ncol]) = o0;
            *reinterpret_cast<float2*>(&out[(size_t)(m0 + 8) * N_DIM + nBase + ncol]) = o1;
        }
    }
}

// ---------- launch ----------
extern "C" void kernel_launch(void* const* d_in, const int* in_sizes, int n_in,
                              void* d_out, int out_size) {
    const float* x    = (const float*)d_in[0];
    const float* w    = (const float*)d_in[1];
    const float* bias = (const float*)d_in[2];
    float* out = (float*)d_out;

    cvt_kernel<<<4096, 256>>>(x, (long)M_DIM * K_DIM / 4, 0);
    cvt_kernel<<<2048, 256>>>(w, (long)N_DIM * K_DIM / 4, 1);

    cudaFuncSetAttribute(bs_f16_kernel, cudaFuncAttributeMaxDynamicSharedMemorySize, SMEM_DYN);
    dim3 grid(N_DIM / BN, M_DIM / BM);   // 16 x 64
    bs_f16_kernel<<<grid, 512, SMEM_DYN>>>(bias, out);
}

// round 8
// speedup vs baseline: 7.5578x; 1.0081x over previous
#include <cuda_runtime.h>
#include <cuda_fp16.h>
#include <cstdint>

// BlockSparse: out = x @ (mask*W)^T + bias.  M=8192, N=4096, K=4096 fp32.
// Mask: 256-blocks, keep (i,j) iff (i+j)%16 >= 8 -> K_eff = 2048 per column block.
//
// R8: fp16 m16n8k16 single pass (rel_err ~3e-4), plus cross-chunk register
// double-buffering of ldmatrix fragments so the tensor pipe never waits on
// LDSM at kstep or chunk boundaries. wait_group<1> makes stage c+1 readable
// one iteration early. Single fused cvt prepass.

#define M_DIM 8192
#define N_DIM 4096
#define K_DIM 4096

#define BM 128
#define BN 256
#define BK 64
#define NCHUNKS 32                        // 8 surviving 256-blocks * (256/64)
#define STAGES 4
#define A_PART (128 * 128)                // 16 KB
#define B_PART (256 * 128)                // 32 KB
#define OFF_A 0
#define OFF_B (A_PART)
#define STAGE_BYTES (A_PART + B_PART)     // 48 KB
#define SMEM_DYN (STAGES * STAGE_BYTES + 2048)

__device__ __half g_x[(size_t)M_DIM * K_DIM];
__device__ __half g_w[(size_t)N_DIM * K_DIM];

// ---------- helpers ----------
__device__ __forceinline__ uint32_t smem_u32(const void* p) {
    uint32_t a;
    asm("{ .reg .u64 t; cvta.to.shared.u64 t, %1; cvt.u32.u64 %0, t; }" : "=r"(a) : "l"(p));
    return a;
}
__device__ __forceinline__ void cp16(uint32_t dst, const void* src) {
    asm volatile("cp.async.cg.shared.global [%0], [%1], 16;" :: "r"(dst), "l"(src));
}
__device__ __forceinline__ void cp_commit() { asm volatile("cp.async.commit_group;" ::: "memory"); }
template <int N> __device__ __forceinline__ void cp_wait() {
    asm volatile("cp.async.wait_group %0;" :: "n"(N) : "memory");
}
__device__ __forceinline__ void ldsm_x4(uint32_t* r, uint32_t addr) {
    asm volatile("ldmatrix.sync.aligned.m8n8.x4.shared.b16 {%0,%1,%2,%3}, [%4];"
                 : "=r"(r[0]), "=r"(r[1]), "=r"(r[2]), "=r"(r[3]) : "r"(addr));
}
__device__ __forceinline__ void mma_f16(float* c, const uint32_t* a, const uint32_t* b) {
    asm volatile(
        "mma.sync.aligned.m16n8k16.row.col.f32.f16.f16.f32 "
        "{%0,%1,%2,%3}, {%4,%5,%6,%7}, {%8,%9}, {%0,%1,%2,%3};"
        : "+f"(c[0]), "+f"(c[1]), "+f"(c[2]), "+f"(c[3])
        : "r"(a[0]), "r"(a[1]), "r"(a[2]), "r"(a[3]), "r"(b[0]), "r"(b[1]));
}
// 128B rows, 8 x 16B chunks; physical chunk = c ^ (r & 7)
__device__ __forceinline__ uint32_t swz(int r, int c) {
    return (uint32_t)(r * 128 + ((c ^ (r & 7)) << 4));
}

// ---------- fused prepass: fp32 -> fp16 for x and w ----------
__global__ __launch_bounds__(256) void cvt_kernel(const float* __restrict__ x,
                                                  const float* __restrict__ w) {
    const long NX = (long)M_DIM * K_DIM / 4;
    const long NT = NX + (long)N_DIM * K_DIM / 4;
    long stride = (long)gridDim.x * blockDim.x;
    for (long j = (long)blockIdx.x * blockDim.x + threadIdx.x; j < NT; j += stride) {
        const bool isx = j < NX;
        const long o = isx ? j : j - NX;
        float4 v = isx ? reinterpret_cast<const float4*>(x)[o]
                       : reinterpret_cast<const float4*>(w)[o];
        __half2 h0 = __floats2half2_rn(v.x, v.y);
        __half2 h1 = __floats2half2_rn(v.z, v.w);
        uint2 pk = make_uint2(*reinterpret_cast<uint32_t*>(&h0),
                              *reinterpret_cast<uint32_t*>(&h1));
        reinterpret_cast<uint2*>(isx ? g_x : g_w)[o] = pk;
    }
}

// ---------- main GEMM ----------
__global__ __launch_bounds__(512, 1)
void bs_f16_kernel(const float* __restrict__ bias, float* __restrict__ out) {
    extern __shared__ char smem[];
    const uint32_t sbase = smem_u32(smem);
    float* sbias = reinterpret_cast<float*>(smem + STAGES * STAGE_BYTES);

    const int tid = threadIdx.x;
    const int wid = tid >> 5;
    const int lane = tid & 31;
    const int nBase = blockIdx.x * BN;
    const int mBase = blockIdx.y * BM;
    const int wm = wid & 1;      // 0..1 over M (64 rows)
    const int wn = wid >> 1;     // 0..7 over N (32 cols)

    int ks[8];
    {
        int n = 0;
        const int i = blockIdx.x;
#pragma unroll
        for (int j = 0; j < 16; j++)
            if (((i + j) & 15) >= 8) ks[n++] = j * 256;
    }

    if (tid < 64) {
        *reinterpret_cast<float4*>(&sbias[tid * 4]) =
            *reinterpret_cast<const float4*>(&bias[nBase + tid * 4]);
    }

    // loader: 3072 x 16B per stage, 6 per thread
    auto load_chunk = [&](int c, int s) {
        const int k0 = ks[c >> 2] + (c & 3) * BK;
        const uint32_t st = sbase + (uint32_t)s * STAGE_BYTES;
#pragma unroll
        for (int i = 0; i < 6; i++) {
            const int idx = tid + i * 512;
            uint32_t dst;
            const __half* src;
            if (idx < 1024) {
                const int r = idx >> 3, cc = idx & 7;
                src = g_x + ((size_t)(mBase + r) * K_DIM + k0 + cc * 8);
                dst = st + OFF_A + swz(r, cc);
            } else {
                const int t = idx - 1024;
                const int r = t >> 3, cc = t & 7;
                src = g_w + ((size_t)(nBase + r) * K_DIM + k0 + cc * 8);
                dst = st + OFF_B + swz(r, cc);
            }
            cp16(dst, src);
        }
        cp_commit();
    };

    // fragment addressing. Row bases are multiples of 8 -> (row & 7) == (lane & 7)
    const int q = lane >> 3;         // ldmatrix quadrant
    const int l7 = lane & 7;
    const int qa = q >> 1;           // A k-half select
    const int qb = q & 1;            // B k-half select
    // A base row: wm*64 + ((q&1)<<3) + l7 ; tiles mi at +16 rows
    const uint32_t aOff0 = OFF_A + (uint32_t)(wm * 64 + ((q & 1) << 3) + l7) * 128;
    // B base row: wn*32 + ((q>>1)<<3) + l7 ; tiles nip at +16 rows
    const uint32_t bOff0 = OFF_B + (uint32_t)(wn * 32 + ((q >> 1) << 3) + l7) * 128;

    auto ldA = [&](uint32_t stb, int kk, uint32_t (*dst)[4]) {
        const uint32_t t = (uint32_t)(((2 * kk + qa) ^ l7) << 4);
#pragma unroll
        for (int mi = 0; mi < 4; mi++)
            ldsm_x4(dst[mi], stb + aOff0 + (uint32_t)(mi * 16 * 128) + t);
    };
    auto ldB = [&](uint32_t stb, int kk, uint32_t* dst) {
        const uint32_t t = (uint32_t)(((2 * kk + qb) ^ l7) << 4);
#pragma unroll
        for (int nip = 0; nip < 2; nip++)
            ldsm_x4(dst + nip * 4, stb + bOff0 + (uint32_t)(nip * 16 * 128) + t);
    };

    float acc[4][4][4];
#pragma unroll
    for (int a = 0; a < 4; a++)
#pragma unroll
        for (int b = 0; b < 4; b++)
#pragma unroll
            for (int p = 0; p < 4; p++) acc[a][b][p] = 0.0f;

    uint32_t af[2][4][4];            // double-buffered A fragments
    uint32_t bf[2][8];               // double-buffered B fragments

    load_chunk(0, 0);
    load_chunk(1, 1);
    load_chunk(2, 2);
    cp_wait<2>();
    __syncthreads();
    ldA(sbase, 0, af[0]);
    ldB(sbase, 0, bf[0]);

#pragma unroll 1
    for (int c = 0; c < NCHUNKS; c++) {
        // need groups <= c+1 complete (cross-chunk frag prefetch reads stage c+1)
        if (c >= NCHUNKS - 2) cp_wait<0>(); else cp_wait<1>();
        __syncthreads();
        if (c + 3 < NCHUNKS) load_chunk(c + 3, (c + 3) & (STAGES - 1));

        const uint32_t st  = sbase + (uint32_t)(c & (STAGES - 1)) * STAGE_BYTES;
        const uint32_t stn = sbase + (uint32_t)((c + 1) & (STAGES - 1)) * STAGE_BYTES;

#pragma unroll
        for (int kstep = 0; kstep < 4; kstep++) {
            const int cur = kstep & 1, nxt = cur ^ 1;
            // prefetch next fragments (next kstep, or next chunk's kstep 0)
            if (kstep < 3) {
                ldA(st, kstep + 1, af[nxt]);
                ldB(st, kstep + 1, bf[nxt]);
            } else if (c + 1 < NCHUNKS) {
                ldA(stn, 0, af[nxt]);
                ldB(stn, 0, bf[nxt]);
            }
            // 16 MMAs on the current fragments
#pragma unroll
            for (int nip = 0; nip < 2; nip++)
#pragma unroll
                for (int half = 0; half < 2; half++) {
                    const int ni = nip * 2 + half;
#pragma unroll
                    for (int mi = 0; mi < 4; mi++)
                        mma_f16(acc[mi][ni], af[cur][mi], &bf[cur][nip * 4 + half * 2]);
                }
        }
    }

    // epilogue: + bias
    const int qid = lane >> 2;
    const int qn = (lane & 3) * 2;
#pragma unroll
    for (int mi = 0; mi < 4; mi++) {
        const int m0 = mBase + wm * 64 + mi * 16 + qid;
#pragma unroll
        for (int ni = 0; ni < 4; ni++) {
            const int ncol = wn * 32 + ni * 8 + qn;
            const float b0 = sbias[ncol], b1 = sbias[ncol + 1];
            float2 o0 = make_float2(acc[mi][ni][0] + b0, acc[mi][ni][1] + b1);
            float2 o1 = make_float2(acc[mi][ni][2] + b0, acc[mi][ni][3] + b1);
            *reinterpret_cast<float2*>(&out[(size_t)m0 * N_DIM + nBase + ncol]) = o0;
            *reinterpret_cast<float2*>(&out[(size_t)(m0 + 8) * N_DIM + nBase + ncol]) = o1;
        }
    }
}

// ---------- launch ----------
extern "C" void kernel_launch(void* const* d_in, const int* in_sizes, int n_in,
                              void* d_out, int out_size) {
    const float* x    = (const float*)d_in[0];
    const float* w    = (const float*)d_in[1];
    const float* bias = (const float*)d_in[2];
    float* out = (float*)d_out;

    cvt_kernel<<<6144, 256>>>(x, w);

    cudaFuncSetAttribute(bs_f16_kernel, cudaFuncAttributeMaxDynamicSharedMemorySize, SMEM_DYN);
    dim3 grid(N_DIM / BN, M_DIM / BM);   // 16 x 64
    bs_f16_kernel<<<grid, 512, SMEM_DYN>>>(bias, out);
}

// round 9
// speedup vs baseline: 7.8535x; 1.0391x over previous
#include <cuda_runtime.h>
#include <cuda_fp16.h>
#include <cstdint>

// BlockSparse: out = x @ (mask*W)^T + bias.  M=8192, N=4096, K=4096 fp32.
// Mask: 256-blocks, keep (i,j) iff (i+j)%16 >= 8 -> K_eff = 2048 per column block.
//
// R9: fp16 m16n8k16 single pass. 256 threads, warp tile 64x64 (2x4 grid) to
// halve smem crossbar traffic vs R8's 16x(64x32); cross-chunk register
// double-buffering of fragments retained. CTA tile 128x256, BK=64, 4 stages.

#define M_DIM 8192
#define N_DIM 4096
#define K_DIM 4096

#define BM 128
#define BN 256
#define BK 64
#define NCHUNKS 32
#define STAGES 4
#define A_PART (128 * 128)                // 16 KB
#define B_PART (256 * 128)                // 32 KB
#define OFF_A 0
#define OFF_B (A_PART)
#define STAGE_BYTES (A_PART + B_PART)     // 48 KB
#define SMEM_DYN (STAGES * STAGE_BYTES + 2048)

__device__ __half g_x[(size_t)M_DIM * K_DIM];
__device__ __half g_w[(size_t)N_DIM * K_DIM];

// ---------- helpers ----------
__device__ __forceinline__ uint32_t smem_u32(const void* p) {
    uint32_t a;
    asm("{ .reg .u64 t; cvta.to.shared.u64 t, %1; cvt.u32.u64 %0, t; }" : "=r"(a) : "l"(p));
    return a;
}
__device__ __forceinline__ void cp16(uint32_t dst, const void* src) {
    asm volatile("cp.async.cg.shared.global [%0], [%1], 16;" :: "r"(dst), "l"(src));
}
__device__ __forceinline__ void cp_commit() { asm volatile("cp.async.commit_group;" ::: "memory"); }
template <int N> __device__ __forceinline__ void cp_wait() {
    asm volatile("cp.async.wait_group %0;" :: "n"(N) : "memory");
}
__device__ __forceinline__ void ldsm_x4(uint32_t* r, uint32_t addr) {
    asm volatile("ldmatrix.sync.aligned.m8n8.x4.shared.b16 {%0,%1,%2,%3}, [%4];"
                 : "=r"(r[0]), "=r"(r[1]), "=r"(r[2]), "=r"(r[3]) : "r"(addr));
}
__device__ __forceinline__ void mma_f16(float* c, const uint32_t* a, const uint32_t* b) {
    asm volatile(
        "mma.sync.aligned.m16n8k16.row.col.f32.f16.f16.f32 "
        "{%0,%1,%2,%3}, {%4,%5,%6,%7}, {%8,%9}, {%0,%1,%2,%3};"
        : "+f"(c[0]), "+f"(c[1]), "+f"(c[2]), "+f"(c[3])
        : "r"(a[0]), "r"(a[1]), "r"(a[2]), "r"(a[3]), "r"(b[0]), "r"(b[1]));
}
__device__ __forceinline__ uint32_t swz(int r, int c) {
    return (uint32_t)(r * 128 + ((c ^ (r & 7)) << 4));
}

// ---------- fused prepass: fp32 -> fp16 ----------
__global__ __launch_bounds__(256) void cvt_kernel(const float* __restrict__ x,
                                                  const float* __restrict__ w) {
    const long NX = (long)M_DIM * K_DIM / 4;
    const long NT = NX + (long)N_DIM * K_DIM / 4;
    long stride = (long)gridDim.x * blockDim.x;
    for (long j = (long)blockIdx.x * blockDim.x + threadIdx.x; j < NT; j += stride) {
        const bool isx = j < NX;
        const long o = isx ? j : j - NX;
        float4 v = isx ? reinterpret_cast<const float4*>(x)[o]
                       : reinterpret_cast<const float4*>(w)[o];
        __half2 h0 = __floats2half2_rn(v.x, v.y);
        __half2 h1 = __floats2half2_rn(v.z, v.w);
        uint2 pk = make_uint2(*reinterpret_cast<uint32_t*>(&h0),
                              *reinterpret_cast<uint32_t*>(&h1));
        reinterpret_cast<uint2*>(isx ? g_x : g_w)[o] = pk;
    }
}

// ---------- main GEMM ----------
__global__ __launch_bounds__(256, 1)
void bs_f16_kernel(const float* __restrict__ bias, float* __restrict__ out) {
    extern __shared__ char smem[];
    const uint32_t sbase = smem_u32(smem);
    float* sbias = reinterpret_cast<float*>(smem + STAGES * STAGE_BYTES);

    const int tid = threadIdx.x;
    const int wid = tid >> 5;
    const int lane = tid & 31;
    const int nBase = blockIdx.x * BN;
    const int mBase = blockIdx.y * BM;
    const int wm = wid & 1;      // 0..1 over M (64 rows)
    const int wn = wid >> 1;     // 0..3 over N (64 cols)

    int ks[8];
    {
        int n = 0;
        const int i = blockIdx.x;
#pragma unroll
        for (int j = 0; j < 16; j++)
            if (((i + j) & 15) >= 8) ks[n++] = j * 256;
    }

    if (tid < 64) {
        *reinterpret_cast<float4*>(&sbias[tid * 4]) =
            *reinterpret_cast<const float4*>(&bias[nBase + tid * 4]);
    }

    // loader: 3072 x 16B per stage, 12 per thread (256 threads)
    auto load_chunk = [&](int c, int s) {
        const int k0 = ks[c >> 2] + (c & 3) * BK;
        const uint32_t st = sbase + (uint32_t)s * STAGE_BYTES;
#pragma unroll
        for (int i = 0; i < 12; i++) {
            const int idx = tid + i * 256;
            uint32_t dst;
            const __half* src;
            if (idx < 1024) {
                const int r = idx >> 3, cc = idx & 7;
                src = g_x + ((size_t)(mBase + r) * K_DIM + k0 + cc * 8);
                dst = st + OFF_A + swz(r, cc);
            } else {
                const int t = idx - 1024;
                const int r = t >> 3, cc = t & 7;
                src = g_w + ((size_t)(nBase + r) * K_DIM + k0 + cc * 8);
                dst = st + OFF_B + swz(r, cc);
            }
            cp16(dst, src);
        }
        cp_commit();
    };

    // fragment addressing (row bases multiples of 8 -> row&7 == lane&7)
    const int q = lane >> 3;
    const int l7 = lane & 7;
    const int qa = q >> 1;           // A k-half select
    const int qb = q & 1;            // B k-half select
    const uint32_t aOff0 = OFF_A + (uint32_t)(wm * 64 + ((q & 1) << 3) + l7) * 128;
    const uint32_t bOff0 = OFF_B + (uint32_t)(wn * 64 + ((q >> 1) << 3) + l7) * 128;

    auto ldA = [&](uint32_t stb, int kk, uint32_t (*dst)[4]) {
        const uint32_t t = (uint32_t)(((2 * kk + qa) ^ l7) << 4);
#pragma unroll
        for (int mi = 0; mi < 4; mi++)
            ldsm_x4(dst[mi], stb + aOff0 + (uint32_t)(mi * 16 * 128) + t);
    };
    auto ldB = [&](uint32_t stb, int kk, uint32_t* dst) {
        const uint32_t t = (uint32_t)(((2 * kk + qb) ^ l7) << 4);
#pragma unroll
        for (int nip = 0; nip < 4; nip++)
            ldsm_x4(dst + nip * 4, stb + bOff0 + (uint32_t)(nip * 16 * 128) + t);
    };

    float acc[4][8][4];
#pragma unroll
    for (int a = 0; a < 4; a++)
#pragma unroll
        for (int b = 0; b < 8; b++)
#pragma unroll
            for (int p = 0; p < 4; p++) acc[a][b][p] = 0.0f;

    uint32_t af[2][4][4];            // double-buffered A fragments (32 regs)
    uint32_t bf[2][16];              // double-buffered B fragments (32 regs)

    load_chunk(0, 0);
    load_chunk(1, 1);
    load_chunk(2, 2);
    cp_wait<2>();
    __syncthreads();
    ldA(sbase, 0, af[0]);
    ldB(sbase, 0, bf[0]);

#pragma unroll 1
    for (int c = 0; c < NCHUNKS; c++) {
        if (c >= NCHUNKS - 2) cp_wait<0>(); else cp_wait<1>();
        __syncthreads();
        if (c + 3 < NCHUNKS) load_chunk(c + 3, (c + 3) & (STAGES - 1));

        const uint32_t st  = sbase + (uint32_t)(c & (STAGES - 1)) * STAGE_BYTES;
        const uint32_t stn = sbase + (uint32_t)((c + 1) & (STAGES - 1)) * STAGE_BYTES;

#pragma unroll
        for (int kstep = 0; kstep < 4; kstep++) {
            const int cur = kstep & 1, nxt = cur ^ 1;
            if (kstep < 3) {
                ldA(st, kstep + 1, af[nxt]);
                ldB(st, kstep + 1, bf[nxt]);
            } else if (c + 1 < NCHUNKS) {
                ldA(stn, 0, af[nxt]);
                ldB(stn, 0, bf[nxt]);
            }
            // 32 MMAs on current fragments
#pragma unroll
            for (int nip = 0; nip < 4; nip++)
#pragma unroll
                for (int half = 0; half < 2; half++) {
                    const int ni = nip * 2 + half;
#pragma unroll
                    for (int mi = 0; mi < 4; mi++)
                        mma_f16(acc[mi][ni], af[cur][mi], &bf[cur][nip * 4 + half * 2]);
                }
        }
    }

    // epilogue: + bias
    const int qid = lane >> 2;
    const int qn = (lane & 3) * 2;
#pragma unroll
    for (int mi = 0; mi < 4; mi++) {
        const int m0 = mBase + wm * 64 + mi * 16 + qid;
#pragma unroll
        for (int ni = 0; ni < 8; ni++) {
            const int ncol = wn * 64 + ni * 8 + qn;
            const float b0 = sbias[ncol], b1 = sbias[ncol + 1];
            float2 o0 = make_float2(acc[mi][ni][0] + b0, acc[mi][ni][1] + b1);
            float2 o1 = make_float2(acc[mi][ni][2] + b0, acc[mi][ni][3] + b1);
            *reinterpret_cast<float2*>(&out[(size_t)m0 * N_DIM + nBase + ncol]) = o0;
            *reinterpret_cast<float2*>(&out[(size_t)(m0 + 8) * N_DIM + nBase + ncol]) = o1;
        }
    }
}

// ---------- launch ----------
extern "C" void kernel_launch(void* const* d_in, const int* in_sizes, int n_in,
                              void* d_out, int out_size) {
    const float* x    = (const float*)d_in[0];
    const float* w    = (const float*)d_in[1];
    const float* bias = (const float*)d_in[2];
    float* out = (float*)d_out;

    cvt_kernel<<<6144, 256>>>(x, w);

    cudaFuncSetAttribute(bs_f16_kernel, cudaFuncAttributeMaxDynamicSharedMemorySize, SMEM_DYN);
    dim3 grid(N_DIM / BN, M_DIM / BM);   // 16 x 64
    bs_f16_kernel<<<grid, 256, SMEM_DYN>>>(bias, out);
}

// round 10
// speedup vs baseline: 8.1724x; 1.0406x over previous
#include <cuda_runtime.h>
#include <cuda_fp16.h>
#include <cstdint>

// BlockSparse: out = x @ (mask*W)^T + bias.  M=8192, N=4096, K=4096 fp32.
// Mask: 256-blocks, keep (i,j) iff (i+j)%16 >= 8 -> K_eff = 2048 per column block.
//
// R10: fp16 m16n8k16 single pass, 8 warps of 64x64, 4-stage cp.async, BK=64.
// Crossbar smoothing: the 12 cp.async per thread per chunk are issued 3-per-
// kstep inside the MMA loop (instead of one post-barrier burst) so smem writes
// overlap the MMA phase instead of colliding with the LDSM bursts.
// cvt prepass skips the masked-out half of W.

#define M_DIM 8192
#define N_DIM 4096
#define K_DIM 4096

#define BM 128
#define BN 256
#define BK 64
#define NCHUNKS 32
#define STAGES 4
#define A_PART (128 * 128)                // 16 KB
#define B_PART (256 * 128)                // 32 KB
#define OFF_A 0
#define OFF_B (A_PART)
#define STAGE_BYTES (A_PART + B_PART)     // 48 KB
#define SMEM_DYN (STAGES * STAGE_BYTES + 2048)

__device__ __half g_x[(size_t)M_DIM * K_DIM];
__device__ __half g_w[(size_t)N_DIM * K_DIM];

// ---------- helpers ----------
__device__ __forceinline__ uint32_t smem_u32(const void* p) {
    uint32_t a;
    asm("{ .reg .u64 t; cvta.to.shared.u64 t, %1; cvt.u32.u64 %0, t; }" : "=r"(a) : "l"(p));
    return a;
}
__device__ __forceinline__ void cp16(uint32_t dst, const void* src) {
    asm volatile("cp.async.cg.shared.global [%0], [%1], 16;" :: "r"(dst), "l"(src));
}
__device__ __forceinline__ void cp_commit() { asm volatile("cp.async.commit_group;" ::: "memory"); }
template <int N> __device__ __forceinline__ void cp_wait() {
    asm volatile("cp.async.wait_group %0;" :: "n"(N) : "memory");
}
__device__ __forceinline__ void ldsm_x4(uint32_t* r, uint32_t addr) {
    asm volatile("ldmatrix.sync.aligned.m8n8.x4.shared.b16 {%0,%1,%2,%3}, [%4];"
                 : "=r"(r[0]), "=r"(r[1]), "=r"(r[2]), "=r"(r[3]) : "r"(addr));
}
__device__ __forceinline__ void mma_f16(float* c, const uint32_t* a, const uint32_t* b) {
    asm volatile(
        "mma.sync.aligned.m16n8k16.row.col.f32.f16.f16.f32 "
        "{%0,%1,%2,%3}, {%4,%5,%6,%7}, {%8,%9}, {%0,%1,%2,%3};"
        : "+f"(c[0]), "+f"(c[1]), "+f"(c[2]), "+f"(c[3])
        : "r"(a[0]), "r"(a[1]), "r"(a[2]), "r"(a[3]), "r"(b[0]), "r"(b[1]));
}
__device__ __forceinline__ uint32_t swz(int r, int c) {
    return (uint32_t)(r * 128 + ((c ^ (r & 7)) << 4));
}

// ---------- prepass: fp32 -> fp16; W converts only unmasked blocks ----------
__global__ __launch_bounds__(256) void cvt_kernel(const float* __restrict__ x,
                                                  const float* __restrict__ w) {
    const long NX = (long)M_DIM * K_DIM / 4;                  // x float4 count
    const long NW = (long)N_DIM * 8 * 64;                     // kept-w float4 count
    const long NT = NX + NW;
    long stride = (long)gridDim.x * blockDim.x;
    for (long t = (long)blockIdx.x * blockDim.x + threadIdx.x; t < NT; t += stride) {
        long o;
        const float* src;
        if (t < NX) {
            o = t;
            src = x;
        } else {
            const long u = t - NX;
            const int row = (int)(u >> 9);          // 512 float4 per row (8 blocks x 64)
            const int rem = (int)(u & 511);
            const int kb = rem >> 6;                // kept-block index 0..7
            const int f4 = rem & 63;
            const int i = row >> 8;                 // n-block index
            const int j = (8 + kb - (i & 15)) & 15; // kept k-block: (i+j)%16 >= 8
            o = (long)row * (K_DIM / 4) + j * 64 + f4;
            src = w;
        }
        float4 v = reinterpret_cast<const float4*>(src)[o];
        __half2 h0 = __floats2half2_rn(v.x, v.y);
        __half2 h1 = __floats2half2_rn(v.z, v.w);
        uint2 pk = make_uint2(*reinterpret_cast<uint32_t*>(&h0),
                              *reinterpret_cast<uint32_t*>(&h1));
        reinterpret_cast<uint2*>(t < NX ? g_x : g_w)[o] = pk;
    }
}

// ---------- main GEMM ----------
__global__ __launch_bounds__(256, 1)
void bs_f16_kernel(const float* __restrict__ bias, float* __restrict__ out) {
    extern __shared__ char smem[];
    const uint32_t sbase = smem_u32(smem);
    float* sbias = reinterpret_cast<float*>(smem + STAGES * STAGE_BYTES);

    const int tid = threadIdx.x;
    const int wid = tid >> 5;
    const int lane = tid & 31;
    const int nBase = blockIdx.x * BN;
    const int mBase = blockIdx.y * BM;
    const int wm = wid & 1;      // 0..1 over M (64 rows)
    const int wn = wid >> 1;     // 0..3 over N (64 cols)

    int ks[8];
    {
        int n = 0;
        const int i = blockIdx.x;
#pragma unroll
        for (int j = 0; j < 16; j++)
            if (((i + j) & 15) >= 8) ks[n++] = j * 256;
    }

    if (tid < 64) {
        *reinterpret_cast<float4*>(&sbias[tid * 4]) =
            *reinterpret_cast<const float4*>(&bias[nBase + tid * 4]);
    }

    // one cp16 transfer (subset ii of 12) for chunk lc into stage st
    auto cp_piece = [&](int lk0, uint32_t st, int ii) {
        const int idx = tid + ii * 256;
        uint32_t dst;
        const __half* src;
        if (idx < 1024) {
            const int r = idx >> 3, cc = idx & 7;
            src = g_x + ((size_t)(mBase + r) * K_DIM + lk0 + cc * 8);
            dst = st + OFF_A + swz(r, cc);
        } else {
            const int t = idx - 1024;
            const int r = t >> 3, cc = t & 7;
            src = g_w + ((size_t)(nBase + r) * K_DIM + lk0 + cc * 8);
            dst = st + OFF_B + swz(r, cc);
        }
        cp16(dst, src);
    };

    auto load_chunk_all = [&](int c, int s) {
        const int k0 = ks[c >> 2] + (c & 3) * BK;
        const uint32_t st = sbase + (uint32_t)s * STAGE_BYTES;
#pragma unroll
        for (int i = 0; i < 12; i++) cp_piece(k0, st, i);
        cp_commit();
    };

    // fragment addressing (row bases multiples of 8 -> row&7 == lane&7)
    const int q = lane >> 3;
    const int l7 = lane & 7;
    const int qa = q >> 1;
    const int qb = q & 1;
    const uint32_t aOff0 = OFF_A + (uint32_t)(wm * 64 + ((q & 1) << 3) + l7) * 128;
    const uint32_t bOff0 = OFF_B + (uint32_t)(wn * 64 + ((q >> 1) << 3) + l7) * 128;

    auto ldA = [&](uint32_t stb, int kk, uint32_t (*dst)[4]) {
        const uint32_t t = (uint32_t)(((2 * kk + qa) ^ l7) << 4);
#pragma unroll
        for (int mi = 0; mi < 4; mi++)
            ldsm_x4(dst[mi], stb + aOff0 + (uint32_t)(mi * 16 * 128) + t);
    };
    auto ldB = [&](uint32_t stb, int kk, uint32_t* dst) {
        const uint32_t t = (uint32_t)(((2 * kk + qb) ^ l7) << 4);
#pragma unroll
        for (int nip = 0; nip < 4; nip++)
            ldsm_x4(dst + nip * 4, stb + bOff0 + (uint32_t)(nip * 16 * 128) + t);
    };

    float acc[4][8][4];
#pragma unroll
    for (int a = 0; a < 4; a++)
#pragma unroll
        for (int b = 0; b < 8; b++)
#pragma unroll
            for (int p = 0; p < 4; p++) acc[a][b][p] = 0.0f;

    uint32_t af[2][4][4];
    uint32_t bf[2][16];

    load_chunk_all(0, 0);
    load_chunk_all(1, 1);
    load_chunk_all(2, 2);
    cp_wait<2>();
    __syncthreads();
    ldA(sbase, 0, af[0]);
    ldB(sbase, 0, bf[0]);

#pragma unroll 1
    for (int c = 0; c < NCHUNKS; c++) {
        if (c >= NCHUNKS - 2) cp_wait<0>(); else cp_wait<1>();
        __syncthreads();

        const bool doLoad = (c + 3 < NCHUNKS);
        const int lc = doLoad ? c + 3 : 0;
        const int lk0 = ks[lc >> 2] + (lc & 3) * BK;
        const uint32_t lst = sbase + (uint32_t)(lc & (STAGES - 1)) * STAGE_BYTES;

        const uint32_t st  = sbase + (uint32_t)(c & (STAGES - 1)) * STAGE_BYTES;
        const uint32_t stn = sbase + (uint32_t)((c + 1) & (STAGES - 1)) * STAGE_BYTES;

#pragma unroll
        for (int kstep = 0; kstep < 4; kstep++) {
            const int cur = kstep & 1, nxt = cur ^ 1;
            // prefetch next fragments (next kstep, or next chunk's kstep 0)
            if (kstep < 3) {
                ldA(st, kstep + 1, af[nxt]);
                ldB(st, kstep + 1, bf[nxt]);
            } else if (c + 1 < NCHUNKS) {
                ldA(stn, 0, af[nxt]);
                ldB(stn, 0, bf[nxt]);
            }
            // 3 of 12 cp.async pieces for chunk c+3 (spread over ksteps)
            if (doLoad) {
#pragma unroll
                for (int ii = 0; ii < 3; ii++) cp_piece(lk0, lst, kstep * 3 + ii);
            }
            // 32 MMAs on current fragments
#pragma unroll
            for (int nip = 0; nip < 4; nip++)
#pragma unroll
                for (int half = 0; half < 2; half++) {
                    const int ni = nip * 2 + half;
#pragma unroll
                    for (int mi = 0; mi < 4; mi++)
                        mma_f16(acc[mi][ni], af[cur][mi], &bf[cur][nip * 4 + half * 2]);
                }
        }
        if (doLoad) cp_commit();
    }

    // epilogue: + bias
    const int qid = lane >> 2;
    const int qn = (lane & 3) * 2;
#pragma unroll
    for (int mi = 0; mi < 4; mi++) {
        const int m0 = mBase + wm * 64 + mi * 16 + qid;
#pragma unroll
        for (int ni = 0; ni < 8; ni++) {
            const int ncol = wn * 64 + ni * 8 + qn;
            const float b0 = sbias[ncol], b1 = sbias[ncol + 1];
            float2 o0 = make_float2(acc[mi][ni][0] + b0, acc[mi][ni][1] + b1);
            float2 o1 = make_float2(acc[mi][ni][2] + b0, acc[mi][ni][3] + b1);
            *reinterpret_cast<float2*>(&out[(size_t)m0 * N_DIM + nBase + ncol]) = o0;
            *reinterpret_cast<float2*>(&out[(size_t)(m0 + 8) * N_DIM + nBase + ncol]) = o1;
        }
    }
}

// ---------- launch ----------
extern "C" void kernel_launch(void* const* d_in, const int* in_sizes, int n_in,
                              void* d_out, int out_size) {
    const float* x    = (const float*)d_in[0];
    const float* w    = (const float*)d_in[1];
    const float* bias = (const float*)d_in[2];
    float* out = (float*)d_out;

    cvt_kernel<<<6144, 256>>>(x, w);

    cudaFuncSetAttribute(bs_f16_kernel, cudaFuncAttributeMaxDynamicSharedMemorySize, SMEM_DYN);
    dim3 grid(N_DIM / BN, M_DIM / BM);   // 16 x 64
    bs_f16_kernel<<<grid, 256, SMEM_DYN>>>(bias, out);
}